// round 16
// baseline (speedup 1.0000x reference)
#include <cuda_runtime.h>
#include <cuda_fp16.h>
#include <cstdint>
#include <math.h>

#define T_SEQ 4096
#define DMODEL 1024
#define NHEADS 16
#define DH 64
#define WIN 256

// ---------------------------------------------------------------------------
// Scratch (__device__ globals; allocation-free rule). All fp16, single copy.
// ---------------------------------------------------------------------------
__device__ __align__(16) __half g_x16[T_SEQ * DMODEL];
__device__ __align__(16) __half g_W16[4 * DMODEL * DMODEL];
__device__ __align__(16) __half g_ao16[T_SEQ * DMODEL];
__device__ __align__(16) __half g_Q16[NHEADS * T_SEQ * DH];   // [h][t][d], *0.125*log2e
__device__ __align__(16) __half g_K16[NHEADS * T_SEQ * DH];   // [h][t][d]
__device__ __align__(16) __half g_Vt16[NHEADS * DH * T_SEQ];  // [h][d][t]

// ---------------------------------------------------------------------------
// PTX helpers (generic PTX only)
// ---------------------------------------------------------------------------
__device__ __forceinline__ uint32_t smem_u32(const void* p) {
    uint32_t a;
    asm("{ .reg .u64 t; cvta.to.shared.u64 t, %1; cvt.u32.u64 %0, t; }"
        : "=r"(a) : "l"(p));
    return a;
}

__device__ __forceinline__ void cp16(uint32_t dst, const void* src) {
    asm volatile("cp.async.cg.shared.global [%0], [%1], 16;" :: "r"(dst), "l"(src));
}
#define CP_COMMIT() asm volatile("cp.async.commit_group;" ::: "memory")
#define CP_WAIT(n)  asm volatile("cp.async.wait_group %0;" :: "n"(n) : "memory")

__device__ __forceinline__ void ldsm4(uint32_t (&r)[4], uint32_t addr) {
    asm volatile("ldmatrix.sync.aligned.m8n8.x4.shared.b16 {%0,%1,%2,%3}, [%4];"
                 : "=r"(r[0]), "=r"(r[1]), "=r"(r[2]), "=r"(r[3]) : "r"(addr));
}

__device__ __forceinline__ void mmah(float (&d)[4], const uint32_t (&a)[4],
                                     uint32_t b0, uint32_t b1) {
    asm volatile(
        "mma.sync.aligned.m16n8k16.row.col.f32.f16.f16.f32 "
        "{%0,%1,%2,%3}, {%4,%5,%6,%7}, {%8,%9}, {%0,%1,%2,%3};"
        : "+f"(d[0]), "+f"(d[1]), "+f"(d[2]), "+f"(d[3])
        : "r"(a[0]), "r"(a[1]), "r"(a[2]), "r"(a[3]), "r"(b0), "r"(b1));
}

__device__ __forceinline__ uint32_t packh(float x, float y) {
    __half hx = __float2half_rn(x), hy = __float2half_rn(y);
    return (uint32_t)__half_as_ushort(hx) | ((uint32_t)__half_as_ushort(hy) << 16);
}

__device__ __forceinline__ float ex2(float x) {
    float r;
    asm("ex2.approx.f32 %0, %1;" : "=f"(r) : "f"(x));
    return r;
}

#define SW128(o) ((o) ^ (((o) >> 3) & 0x70))

// ---------------------------------------------------------------------------
// fused fp32 -> fp16 conversion (x + all 4 weights, one launch)
// ---------------------------------------------------------------------------
__global__ void convAll(const float* __restrict__ x,
                        const float* __restrict__ W0, const float* __restrict__ W1,
                        const float* __restrict__ W2, const float* __restrict__ W3,
                        __half* __restrict__ x16, __half* __restrict__ W16) {
    const int WSZ = DMODEL * DMODEL;
    int b = blockIdx.x;
    const float* src;
    __half* dst;
    int i;
    if (b < 4096) {
        src = x; dst = x16; i = b * 256 + threadIdx.x;
    } else {
        int w = (b - 4096) >> 10;
        int lb = (b - 4096) & 1023;
        src = (w == 0) ? W0 : (w == 1) ? W1 : (w == 2) ? W2 : W3;
        dst = W16 + (size_t)w * WSZ;
        i = lb * 256 + threadIdx.x;
    }
    float4 v = ((const float4*)src)[i];
    uint2 o;
    o.x = packh(v.x, v.y);
    o.y = packh(v.z, v.w);
    ((uint2*)dst)[i] = o;
}

// ---------------------------------------------------------------------------
// fp16 GEMM (R15 proven: 5-stage ring, one sync per chunk, 2 CTAs/SM)
// ---------------------------------------------------------------------------
#define KC 32
#define ROWB 80
#define TILE_B (128 * ROWB)
#define OFF_A 0
#define OFF_B TILE_B
#define STAGE_B (2 * TILE_B)             // 20480
#define NSTAGE 5
#define GEMM_SMEM (NSTAGE * STAGE_B)     // 102400
#define NCH (DMODEL / KC)                // 32

__device__ __forceinline__ void gemm_issue(
    uint32_t sb, int stage, int chunk,
    const __half* __restrict__ A, const __half* __restrict__ B,
    int bm, int bn, int tid) {
    const uint32_t st = sb + (uint32_t)stage * STAGE_B;
    const __half* aA = A + (size_t)bm * DMODEL;
    const __half* bB = B + (size_t)bn * DMODEL;
#pragma unroll
    for (int i = 0; i < 2; i++) {
        int slot = tid + i * 256;
        int row = slot >> 2, seg = slot & 3;
        uint32_t off = row * ROWB + seg * 16;
        const size_t g = (size_t)row * DMODEL + chunk * KC + seg * 8;
        cp16(st + OFF_A + off, aA + g);
        cp16(st + OFF_B + off, bB + g);
    }
    CP_COMMIT();
}

__device__ __forceinline__ void gemm_main(
    uint32_t sb, const __half* __restrict__ A, const __half* __restrict__ B,
    int bm, int bn, int tid, int wm, int wn, int lrow, int lseg,
    float (&acc)[4][4][4]) {
#pragma unroll
    for (int i = 0; i < 4; i++)
#pragma unroll
        for (int j = 0; j < 4; j++)
#pragma unroll
            for (int e = 0; e < 4; e++) acc[i][j][e] = 0.0f;

    gemm_issue(sb, 0, 0, A, B, bm, bn, tid);
    gemm_issue(sb, 1, 1, A, B, bm, bn, tid);
    gemm_issue(sb, 2, 2, A, B, bm, bn, tid);
    gemm_issue(sb, 3, 3, A, B, bm, bn, tid);

    int stage = 0;
    int pstage = 4;
    for (int c = 0; c < NCH; c++) {
        if (c <= NCH - 4) { CP_WAIT(3); }
        else if (c == NCH - 3) { CP_WAIT(2); }
        else if (c == NCH - 2) { CP_WAIT(1); }
        else { CP_WAIT(0); }
        __syncthreads();

        if (c + 4 < NCH)
            gemm_issue(sb, pstage, c + 4, A, B, bm, bn, tid);

        const uint32_t st = sb + (uint32_t)stage * STAGE_B;
#pragma unroll
        for (int kk = 0; kk < 2; kk++) {
            uint32_t af[4][4];
            uint32_t bf[2][4];
#pragma unroll
            for (int mi = 0; mi < 4; mi++) {
                uint32_t ad = st + OFF_A + (wm + mi * 16 + lrow) * ROWB + kk * 32 + lseg * 16;
                ldsm4(af[mi], ad);
            }
#pragma unroll
            for (int n16 = 0; n16 < 2; n16++) {
                uint32_t ad = st + OFF_B + (wn + n16 * 16 + lrow) * ROWB + kk * 32 + lseg * 16;
                ldsm4(bf[n16], ad);
            }
#pragma unroll
            for (int mi = 0; mi < 4; mi++)
#pragma unroll
                for (int nj = 0; nj < 4; nj++) {
                    const int nh = nj >> 1, sub = nj & 1;
                    mmah(acc[mi][nj], af[mi], bf[nh][sub], bf[nh][sub + 2]);
                }
        }
        stage = (stage == 4) ? 0 : stage + 1;
        pstage = (pstage == 4) ? 0 : pstage + 1;
    }
}

__device__ __forceinline__ void epi_head(
    const float (&acc)[4][4][4], __half* __restrict__ Ch, float scale,
    int r0, int c0) {
#pragma unroll
    for (int mi = 0; mi < 4; mi++)
#pragma unroll
        for (int nj = 0; nj < 4; nj++) {
            const int r = r0 + mi * 16;
            const int cc = c0 + nj * 8;
            const int h = cc >> 6;
            const int cl = cc & 63;
#pragma unroll
            for (int half = 0; half < 2; half++) {
                float v0 = acc[mi][nj][half * 2 + 0] * scale;
                float v1 = acc[mi][nj][half * 2 + 1] * scale;
                size_t base = ((size_t)(h * T_SEQ + r + half * 8) << 6) + cl;
                *(uint32_t*)(Ch + base) = packh(v0, v1);
            }
        }
}

__global__ void __launch_bounds__(256, 2)
gemm_qkv(const __half* __restrict__ A, const __half* __restrict__ W,
         __half* __restrict__ Q, __half* __restrict__ K, __half* __restrict__ Vt,
         int bmoff) {
    extern __shared__ char smraw[];
    const uint32_t sb = smem_u32(smraw);

    const int tid = threadIdx.x;
    const int warp = tid >> 5;
    const int lane = tid & 31;
    const int bm = bmoff + blockIdx.y * 128;
    const int bn = blockIdx.x * 128;
    const int z = blockIdx.z;
    const int wm = (warp >> 2) * 64;
    const int wn = (warp & 3) * 32;
    const int lrow = lane & 15;
    const int lseg = lane >> 4;

    const __half* B = W + (size_t)z * DMODEL * DMODEL;

    float acc[4][4][4];
    gemm_main(sb, A, B, bm, bn, tid, wm, wn, lrow, lseg, acc);

    const int r0 = bm + wm + (lane >> 2);
    const int c0 = bn + wn + (lane & 3) * 2;

    if (z == 0) {
        epi_head(acc, Q, 0.18033688011112042f, r0, c0);
    } else if (z == 1) {
        epi_head(acc, K, 1.0f, r0, c0);
    } else {
        __syncthreads();
        __half* sV = (__half*)smraw;          // [128 n][136 m-pad]
        const int lr0 = wm + (lane >> 2);
        const int lc0 = wn + (lane & 3) * 2;
#pragma unroll
        for (int mi = 0; mi < 4; mi++)
#pragma unroll
            for (int nj = 0; nj < 4; nj++) {
                const int lc = lc0 + nj * 8;
#pragma unroll
                for (int half = 0; half < 2; half++) {
                    int rr = lr0 + mi * 16 + half * 8;
                    sV[lc * 136 + rr] = __float2half_rn(acc[mi][nj][half * 2 + 0]);
                    sV[(lc + 1) * 136 + rr] = __float2half_rn(acc[mi][nj][half * 2 + 1]);
                }
            }
        __syncthreads();
        for (int i = tid; i < 128 * 16; i += 256) {
            int row = i >> 4, seg = i & 15;
            int gn = bn + row;
            int hh = gn >> 6, dd = gn & 63;
            size_t dst = (size_t)(hh * DH + dd) * T_SEQ + bm + seg * 8;
            *(uint4*)(Vt + dst) = *(uint4*)(sV + row * 136 + seg * 8);
        }
    }
}

__global__ void __launch_bounds__(256, 2)
gemm_out(const __half* __restrict__ A, const __half* __restrict__ B,
         float* __restrict__ Cf, int bmoff) {
    extern __shared__ char smraw[];
    const uint32_t sb = smem_u32(smraw);

    const int tid = threadIdx.x;
    const int warp = tid >> 5;
    const int lane = tid & 31;
    const int bm = bmoff + blockIdx.y * 128;
    const int bn = blockIdx.x * 128;
    const int wm = (warp >> 2) * 64;
    const int wn = (warp & 3) * 32;
    const int lrow = lane & 15;
    const int lseg = lane >> 4;

    float acc[4][4][4];
    gemm_main(sb, A, B, bm, bn, tid, wm, wn, lrow, lseg, acc);

    const int r0 = bm + wm + (lane >> 2);
    const int c0 = bn + wn + (lane & 3) * 2;
#pragma unroll
    for (int mi = 0; mi < 4; mi++)
#pragma unroll
        for (int nj = 0; nj < 4; nj++) {
            const int r = r0 + mi * 16;
            const int cc = c0 + nj * 8;
            float* d0 = Cf + (size_t)r * DMODEL + cc;
            float* d1 = Cf + (size_t)(r + 8) * DMODEL + cc;
            *(float2*)d0 = make_float2(acc[mi][nj][0], acc[mi][nj][1]);
            *(float2*)d1 = make_float2(acc[mi][nj][2], acc[mi][nj][3]);
        }
}

// ---------------------------------------------------------------------------
// fp16 HMMA sliding-window attention (R13/R15 proven; +qoff parameter)
// ---------------------------------------------------------------------------
#define AT_ROWB 128
#define ATILE (64 * AT_ROWB)              // 8192
#define AOFF_K 0
#define AOFF_V ATILE
#define ASTAGE (2 * ATILE)                // 16384
#define ANSTAGE 4
#define AOFF_Q (ANSTAGE * ASTAGE)         // 65536
#define ATTN_SMEM (AOFF_Q + ATILE)        // 73728

__device__ __forceinline__ void attn_load_tile(
    uint32_t base, const __half* __restrict__ K16, const __half* __restrict__ Vt16,
    int h, int kt, int tid) {
#pragma unroll
    for (int i = 0; i < 4; i++) {
        int idx = tid + i * 128;
        int row = idx >> 3, seg = idx & 7;
        uint32_t off = SW128((uint32_t)(row * AT_ROWB + seg * 16));
        size_t ks = ((size_t)(h * T_SEQ + kt + row) << 6) + seg * 8;
        cp16(base + AOFF_K + off, K16 + ks);
        size_t vs = (size_t)(h * DH + row) * T_SEQ + kt + seg * 8;
        cp16(base + AOFF_V + off, Vt16 + vs);
    }
    CP_COMMIT();
}

__global__ void __launch_bounds__(128)
attn_mma(const __half* __restrict__ Q16, const __half* __restrict__ K16,
         const __half* __restrict__ Vt16, __half* __restrict__ AO, int qoff) {
    extern __shared__ char smraw[];
    const uint32_t sb = smem_u32(smraw);
    const int tid = threadIdx.x;
    const int warp = tid >> 5;
    const int lane = tid & 31;
    const int h = blockIdx.y;
    const int q0 = qoff + blockIdx.x * 64;
    const int lrow = lane & 15;
    const int lseg = lane >> 4;

    const int kt_lo = (q0 >= WIN) ? (q0 - WIN) : 0;
    const int ntiles = (q0 - kt_lo) / 64 + 1;   // 1..5

#pragma unroll
    for (int i = 0; i < 4; i++) {
        int idx = tid + i * 128;
        int row = idx >> 3, seg = idx & 7;
        uint32_t dst = sb + AOFF_Q + SW128((uint32_t)(row * AT_ROWB + seg * 16));
        size_t qs = ((size_t)(h * T_SEQ + q0 + row) << 6) + seg * 8;
        cp16(dst, Q16 + qs);
    }
    CP_COMMIT();
    attn_load_tile(sb, K16, Vt16, h, kt_lo, tid);
    if (ntiles > 1) attn_load_tile(sb + ASTAGE, K16, Vt16, h, kt_lo + 64, tid);
    if (ntiles > 2) attn_load_tile(sb + 2 * ASTAGE, K16, Vt16, h, kt_lo + 128, tid);

    if (ntiles > 2)      { CP_WAIT(3); }
    else if (ntiles > 1) { CP_WAIT(2); }
    else                 { CP_WAIT(1); }
    __syncthreads();

    uint32_t qf[4][4];
#pragma unroll
    for (int k = 0; k < 4; k++) {
        uint32_t ad = sb + AOFF_Q +
                      SW128((uint32_t)((warp * 16 + lrow) * AT_ROWB + k * 32 + lseg * 16));
        ldsm4(qf[k], ad);
    }

    float o[8][4];
#pragma unroll
    for (int j = 0; j < 8; j++)
#pragma unroll
        for (int e = 0; e < 4; e++) o[j][e] = 0.0f;
    float m0 = -1e30f, m1 = -1e30f, l0 = 0.0f, l1 = 0.0f;

    for (int ti = 0; ti < ntiles; ti++) {
        const int kt = kt_lo + ti * 64;
        if (ti <= ntiles - 3) { CP_WAIT(2); }
        else if (ti == ntiles - 2) { CP_WAIT(1); }
        else { CP_WAIT(0); }
        __syncthreads();

        if (ti + 3 < ntiles)
            attn_load_tile(sb + (uint32_t)((ti + 3) & 3) * ASTAGE, K16, Vt16, h,
                           kt + 192, tid);

        const uint32_t base = sb + (uint32_t)(ti & 3) * ASTAGE;

        float sf[8][4];
#pragma unroll
        for (int j = 0; j < 8; j++)
#pragma unroll
            for (int e = 0; e < 4; e++) sf[j][e] = 0.0f;
#pragma unroll
        for (int kk = 0; kk < 4; kk++) {
            uint32_t bf[4][4];
#pragma unroll
            for (int n16 = 0; n16 < 4; n16++) {
                uint32_t ad = base + AOFF_K +
                    SW128((uint32_t)((n16 * 16 + lrow) * AT_ROWB + kk * 32 + lseg * 16));
                ldsm4(bf[n16], ad);
            }
#pragma unroll
            for (int j = 0; j < 8; j++) {
                const int nh = j >> 1, sub = j & 1;
                mmah(sf[j], qf[kk], bf[nh][sub], bf[nh][sub + 2]);
            }
        }

        const int r0 = q0 + warp * 16 + (lane >> 2);
        const int r1 = r0 + 8;
#pragma unroll
        for (int j = 0; j < 8; j++) {
            const int c0 = kt + 8 * j + (lane & 3) * 2;
            const int c1 = c0 + 1;
            if (c0 > r0 || c0 < r0 - WIN) sf[j][0] = -1e30f;
            if (c1 > r0 || c1 < r0 - WIN) sf[j][1] = -1e30f;
            if (c0 > r1 || c0 < r1 - WIN) sf[j][2] = -1e30f;
            if (c1 > r1 || c1 < r1 - WIN) sf[j][3] = -1e30f;
        }

        float t0 = -1e30f, t1 = -1e30f;
#pragma unroll
        for (int j = 0; j < 8; j++) {
            t0 = fmaxf(t0, fmaxf(sf[j][0], sf[j][1]));
            t1 = fmaxf(t1, fmaxf(sf[j][2], sf[j][3]));
        }
        t0 = fmaxf(t0, __shfl_xor_sync(0xffffffffu, t0, 1));
        t0 = fmaxf(t0, __shfl_xor_sync(0xffffffffu, t0, 2));
        t1 = fmaxf(t1, __shfl_xor_sync(0xffffffffu, t1, 1));
        t1 = fmaxf(t1, __shfl_xor_sync(0xffffffffu, t1, 2));
        const float mn0 = fmaxf(m0, t0), mn1 = fmaxf(m1, t1);
        const float corr0 = ex2(m0 - mn0), corr1 = ex2(m1 - mn1);
        m0 = mn0;
        m1 = mn1;

        uint32_t ph[4][4];
        float s0 = 0.0f, s1 = 0.0f;
#pragma unroll
        for (int j = 0; j < 8; j++) {
            float p0 = ex2(sf[j][0] - m0);
            float p1 = ex2(sf[j][1] - m0);
            float p2 = ex2(sf[j][2] - m1);
            float p3 = ex2(sf[j][3] - m1);
            s0 += p0 + p1;
            s1 += p2 + p3;
            const int kk = j >> 1, pos = (j & 1) * 2;
            ph[kk][pos + 0] = packh(p0, p1);
            ph[kk][pos + 1] = packh(p2, p3);
        }
        s0 += __shfl_xor_sync(0xffffffffu, s0, 1);
        s0 += __shfl_xor_sync(0xffffffffu, s0, 2);
        s1 += __shfl_xor_sync(0xffffffffu, s1, 1);
        s1 += __shfl_xor_sync(0xffffffffu, s1, 2);
        l0 = l0 * corr0 + s0;
        l1 = l1 * corr1 + s1;
#pragma unroll
        for (int j = 0; j < 8; j++) {
            o[j][0] *= corr0;
            o[j][1] *= corr0;
            o[j][2] *= corr1;
            o[j][3] *= corr1;
        }

#pragma unroll
        for (int kk = 0; kk < 4; kk++) {
            uint32_t vf[4][4];
#pragma unroll
            for (int n16 = 0; n16 < 4; n16++) {
                uint32_t ad = base + AOFF_V +
                    SW128((uint32_t)((n16 * 16 + lrow) * AT_ROWB + kk * 32 + lseg * 16));
                ldsm4(vf[n16], ad);
            }
#pragma unroll
            for (int j = 0; j < 8; j++) {
                const int nh = j >> 1, sub = j & 1;
                mmah(o[j], ph[kk], vf[nh][sub], vf[nh][sub + 2]);
            }
        }
    }

    const float i0 = 1.0f / l0;
    const float i1 = 1.0f / l1;
    const int tr = q0 + warp * 16 + (lane >> 2);
#pragma unroll
    for (int j = 0; j < 8; j++) {
        const int d = 8 * j + (lane & 3) * 2;
        size_t a0 = (size_t)tr * DMODEL + h * DH + d;
        size_t a1 = (size_t)(tr + 8) * DMODEL + h * DH + d;
        *(uint32_t*)(AO + a0) = packh(o[j][0] * i0, o[j][1] * i0);
        *(uint32_t*)(AO + a1) = packh(o[j][2] * i1, o[j][3] * i1);
    }
}

// ---------------------------------------------------------------------------
// Launch: two-stream fork-join pipelining exploiting window locality.
// Half-split dependencies: attn[q<2048] needs only qkv rows <2048 (causal
// window looks back); out[rows<2048] needs only attn[q<2048].
//   s0: conv, qkvA, (e1), qkvB, attnB, outB, wait(eD)
//   s1: wait(e1), attnA, outA, (eD)
// Stream/events are created once on the first (uncaptured) call and only
// used thereafter — standard captured fork-join, no allocations in capture.
// ---------------------------------------------------------------------------
extern "C" void kernel_launch(void* const* d_in, const int* in_sizes, int n_in,
                              void* d_out, int out_size) {
    const float* x  = (const float*)d_in[0];
    const float* Wq = (const float*)d_in[1];
    const float* Wk = (const float*)d_in[2];
    const float* Wv = (const float*)d_in[3];
    const float* Wo = (const float*)d_in[4];
    float* out = (float*)d_out;

    __half *px16, *pW16, *pao16, *pQ16, *pK16, *pVt16;
    cudaGetSymbolAddress((void**)&px16, g_x16);
    cudaGetSymbolAddress((void**)&pW16, g_W16);
    cudaGetSymbolAddress((void**)&pao16, g_ao16);
    cudaGetSymbolAddress((void**)&pQ16, g_Q16);
    cudaGetSymbolAddress((void**)&pK16, g_K16);
    cudaGetSymbolAddress((void**)&pVt16, g_Vt16);

    cudaFuncSetAttribute(gemm_qkv, cudaFuncAttributeMaxDynamicSharedMemorySize, GEMM_SMEM);
    cudaFuncSetAttribute(gemm_out, cudaFuncAttributeMaxDynamicSharedMemorySize, GEMM_SMEM);
    cudaFuncSetAttribute(attn_mma, cudaFuncAttributeMaxDynamicSharedMemorySize, ATTN_SMEM);

    // one-time resources (created on the uncaptured correctness call)
    static cudaStream_t s1 = nullptr;
    static cudaEvent_t e1 = nullptr, eD = nullptr;
    if (s1 == nullptr) {
        cudaStreamCreateWithFlags(&s1, cudaStreamNonBlocking);
        cudaEventCreateWithFlags(&e1, cudaEventDisableTiming);
        cudaEventCreateWithFlags(&eD, cudaEventDisableTiming);
    }
    cudaStream_t s0 = (cudaStream_t)0;   // legacy default stream (captured)

    const int WSZ = DMODEL * DMODEL;
    const int HALF = T_SEQ / 2;          // 2048

    convAll<<<4096 + 4096, 256, 0, s0>>>(x, Wq, Wk, Wv, Wo, px16, pW16);

    dim3 hgrid(DMODEL / 128, HALF / 128, 3);   // (8, 16, 3)
    gemm_qkv<<<hgrid, 256, GEMM_SMEM, s0>>>(px16, pW16, pQ16, pK16, pVt16, 0);
    cudaEventRecord(e1, s0);
    gemm_qkv<<<hgrid, 256, GEMM_SMEM, s0>>>(px16, pW16, pQ16, pK16, pVt16, HALF);

    // s1 branch: first-half attention + first-half output projection
    cudaStreamWaitEvent(s1, e1, 0);
    dim3 agridH(HALF / 64, NHEADS);            // (32, 16)
    attn_mma<<<agridH, 128, ATTN_SMEM, s1>>>(pQ16, pK16, pVt16, pao16, 0);
    dim3 ogridH(DMODEL / 128, HALF / 128);     // (8, 16)
    gemm_out<<<ogridH, 256, GEMM_SMEM, s1>>>(pao16, pW16 + 3 * WSZ, out, 0);
    cudaEventRecord(eD, s1);

    // s0 continues: second-half attention + second-half output projection
    attn_mma<<<agridH, 128, ATTN_SMEM, s0>>>(pQ16, pK16, pVt16, pao16, HALF);
    gemm_out<<<ogridH, 256, GEMM_SMEM, s0>>>(pao16, pW16 + 3 * WSZ, out, HALF);

    // join
    cudaStreamWaitEvent(s0, eD, 0);
}

// round 17
// speedup vs baseline: 1.0191x; 1.0191x over previous
#include <cuda_runtime.h>
#include <cuda_fp16.h>
#include <cstdint>
#include <math.h>

#define T_SEQ 4096
#define DMODEL 1024
#define NHEADS 16
#define DH 64
#define WIN 256

// ---------------------------------------------------------------------------
// Scratch (__device__ globals; allocation-free rule). All fp16, single copy.
// ---------------------------------------------------------------------------
__device__ __align__(16) __half g_x16[T_SEQ * DMODEL];
__device__ __align__(16) __half g_W16[4 * DMODEL * DMODEL];
__device__ __align__(16) __half g_ao16[T_SEQ * DMODEL];
__device__ __align__(16) __half g_Q16[NHEADS * T_SEQ * DH];   // [h][t][d], *0.125*log2e
__device__ __align__(16) __half g_K16[NHEADS * T_SEQ * DH];   // [h][t][d]
__device__ __align__(16) __half g_Vt16[NHEADS * DH * T_SEQ];  // [h][d][t]

// ---------------------------------------------------------------------------
// PTX helpers (generic PTX only)
// ---------------------------------------------------------------------------
__device__ __forceinline__ uint32_t smem_u32(const void* p) {
    uint32_t a;
    asm("{ .reg .u64 t; cvta.to.shared.u64 t, %1; cvt.u32.u64 %0, t; }"
        : "=r"(a) : "l"(p));
    return a;
}

__device__ __forceinline__ void cp16(uint32_t dst, const void* src) {
    asm volatile("cp.async.cg.shared.global [%0], [%1], 16;" :: "r"(dst), "l"(src));
}
#define CP_COMMIT() asm volatile("cp.async.commit_group;" ::: "memory")
#define CP_WAIT(n)  asm volatile("cp.async.wait_group %0;" :: "n"(n) : "memory")

__device__ __forceinline__ void ldsm4(uint32_t (&r)[4], uint32_t addr) {
    asm volatile("ldmatrix.sync.aligned.m8n8.x4.shared.b16 {%0,%1,%2,%3}, [%4];"
                 : "=r"(r[0]), "=r"(r[1]), "=r"(r[2]), "=r"(r[3]) : "r"(addr));
}

__device__ __forceinline__ void mmah(float (&d)[4], const uint32_t (&a)[4],
                                     uint32_t b0, uint32_t b1) {
    asm volatile(
        "mma.sync.aligned.m16n8k16.row.col.f32.f16.f16.f32 "
        "{%0,%1,%2,%3}, {%4,%5,%6,%7}, {%8,%9}, {%0,%1,%2,%3};"
        : "+f"(d[0]), "+f"(d[1]), "+f"(d[2]), "+f"(d[3])
        : "r"(a[0]), "r"(a[1]), "r"(a[2]), "r"(a[3]), "r"(b0), "r"(b1));
}

__device__ __forceinline__ uint32_t packh(float x, float y) {
    __half hx = __float2half_rn(x), hy = __float2half_rn(y);
    return (uint32_t)__half_as_ushort(hx) | ((uint32_t)__half_as_ushort(hy) << 16);
}

__device__ __forceinline__ float ex2(float x) {
    float r;
    asm("ex2.approx.f32 %0, %1;" : "=f"(r) : "f"(x));
    return r;
}

#define SW128(o) ((o) ^ (((o) >> 3) & 0x70))

// ---------------------------------------------------------------------------
// fused fp32 -> fp16 conversion (x + all 4 weights, one launch)
// ---------------------------------------------------------------------------
__global__ void convAll(const float* __restrict__ x,
                        const float* __restrict__ W0, const float* __restrict__ W1,
                        const float* __restrict__ W2, const float* __restrict__ W3,
                        __half* __restrict__ x16, __half* __restrict__ W16) {
    const int WSZ = DMODEL * DMODEL;
    int b = blockIdx.x;
    const float* src;
    __half* dst;
    int i;
    if (b < 4096) {
        src = x; dst = x16; i = b * 256 + threadIdx.x;
    } else {
        int w = (b - 4096) >> 10;
        int lb = (b - 4096) & 1023;
        src = (w == 0) ? W0 : (w == 1) ? W1 : (w == 2) ? W2 : W3;
        dst = W16 + (size_t)w * WSZ;
        i = lb * 256 + threadIdx.x;
    }
    float4 v = ((const float4*)src)[i];
    uint2 o;
    o.x = packh(v.x, v.y);
    o.y = packh(v.z, v.w);
    ((uint2*)dst)[i] = o;
}

// ---------------------------------------------------------------------------
// fp16 GEMM (R15 proven: 5-stage ring, one sync per chunk, 2 CTAs/SM)
// ---------------------------------------------------------------------------
#define KC 32
#define ROWB 80
#define TILE_B (128 * ROWB)
#define OFF_A 0
#define OFF_B TILE_B
#define STAGE_B (2 * TILE_B)             // 20480
#define NSTAGE 5
#define GEMM_SMEM (NSTAGE * STAGE_B)     // 102400
#define NCH (DMODEL / KC)                // 32

__device__ __forceinline__ void gemm_issue(
    uint32_t sb, int stage, int chunk,
    const __half* __restrict__ A, const __half* __restrict__ B,
    int bm, int bn, int tid) {
    const uint32_t st = sb + (uint32_t)stage * STAGE_B;
    const __half* aA = A + (size_t)bm * DMODEL;
    const __half* bB = B + (size_t)bn * DMODEL;
#pragma unroll
    for (int i = 0; i < 2; i++) {
        int slot = tid + i * 256;
        int row = slot >> 2, seg = slot & 3;
        uint32_t off = row * ROWB + seg * 16;
        const size_t g = (size_t)row * DMODEL + chunk * KC + seg * 8;
        cp16(st + OFF_A + off, aA + g);
        cp16(st + OFF_B + off, bB + g);
    }
    CP_COMMIT();
}

__device__ __forceinline__ void gemm_main(
    uint32_t sb, const __half* __restrict__ A, const __half* __restrict__ B,
    int bm, int bn, int tid, int wm, int wn, int lrow, int lseg,
    float (&acc)[4][4][4]) {
#pragma unroll
    for (int i = 0; i < 4; i++)
#pragma unroll
        for (int j = 0; j < 4; j++)
#pragma unroll
            for (int e = 0; e < 4; e++) acc[i][j][e] = 0.0f;

    gemm_issue(sb, 0, 0, A, B, bm, bn, tid);
    gemm_issue(sb, 1, 1, A, B, bm, bn, tid);
    gemm_issue(sb, 2, 2, A, B, bm, bn, tid);
    gemm_issue(sb, 3, 3, A, B, bm, bn, tid);

    int stage = 0;
    int pstage = 4;
    for (int c = 0; c < NCH; c++) {
        if (c <= NCH - 4) { CP_WAIT(3); }
        else if (c == NCH - 3) { CP_WAIT(2); }
        else if (c == NCH - 2) { CP_WAIT(1); }
        else { CP_WAIT(0); }
        __syncthreads();

        if (c + 4 < NCH)
            gemm_issue(sb, pstage, c + 4, A, B, bm, bn, tid);

        const uint32_t st = sb + (uint32_t)stage * STAGE_B;
#pragma unroll
        for (int kk = 0; kk < 2; kk++) {
            uint32_t af[4][4];
            uint32_t bf[2][4];
#pragma unroll
            for (int mi = 0; mi < 4; mi++) {
                uint32_t ad = st + OFF_A + (wm + mi * 16 + lrow) * ROWB + kk * 32 + lseg * 16;
                ldsm4(af[mi], ad);
            }
#pragma unroll
            for (int n16 = 0; n16 < 2; n16++) {
                uint32_t ad = st + OFF_B + (wn + n16 * 16 + lrow) * ROWB + kk * 32 + lseg * 16;
                ldsm4(bf[n16], ad);
            }
#pragma unroll
            for (int mi = 0; mi < 4; mi++)
#pragma unroll
                for (int nj = 0; nj < 4; nj++) {
                    const int nh = nj >> 1, sub = nj & 1;
                    mmah(acc[mi][nj], af[mi], bf[nh][sub], bf[nh][sub + 2]);
                }
        }
        stage = (stage == 4) ? 0 : stage + 1;
        pstage = (pstage == 4) ? 0 : pstage + 1;
    }
}

__device__ __forceinline__ void epi_head(
    const float (&acc)[4][4][4], __half* __restrict__ Ch, float scale,
    int r0, int c0) {
#pragma unroll
    for (int mi = 0; mi < 4; mi++)
#pragma unroll
        for (int nj = 0; nj < 4; nj++) {
            const int r = r0 + mi * 16;
            const int cc = c0 + nj * 8;
            const int h = cc >> 6;
            const int cl = cc & 63;
#pragma unroll
            for (int half = 0; half < 2; half++) {
                float v0 = acc[mi][nj][half * 2 + 0] * scale;
                float v1 = acc[mi][nj][half * 2 + 1] * scale;
                size_t base = ((size_t)(h * T_SEQ + r + half * 8) << 6) + cl;
                *(uint32_t*)(Ch + base) = packh(v0, v1);
            }
        }
}

__global__ void __launch_bounds__(256, 2)
gemm_qkv(const __half* __restrict__ A, const __half* __restrict__ W,
         __half* __restrict__ Q, __half* __restrict__ K, __half* __restrict__ Vt) {
    extern __shared__ char smraw[];
    const uint32_t sb = smem_u32(smraw);

    const int tid = threadIdx.x;
    const int warp = tid >> 5;
    const int lane = tid & 31;
    const int bm = blockIdx.y * 128;
    const int bn = blockIdx.x * 128;
    const int z = blockIdx.z;
    const int wm = (warp >> 2) * 64;
    const int wn = (warp & 3) * 32;
    const int lrow = lane & 15;
    const int lseg = lane >> 4;

    const __half* B = W + (size_t)z * DMODEL * DMODEL;

    float acc[4][4][4];
    gemm_main(sb, A, B, bm, bn, tid, wm, wn, lrow, lseg, acc);

    const int r0 = bm + wm + (lane >> 2);
    const int c0 = bn + wn + (lane & 3) * 2;

    if (z == 0) {
        // Q pre-scaled by (1/sqrt(64)) * log2(e) so softmax uses raw ex2
        epi_head(acc, Q, 0.18033688011112042f, r0, c0);
    } else if (z == 1) {
        epi_head(acc, K, 1.0f, r0, c0);
    } else {
        __syncthreads();
        __half* sV = (__half*)smraw;          // [128 n][136 m-pad]
        const int lr0 = wm + (lane >> 2);
        const int lc0 = wn + (lane & 3) * 2;
#pragma unroll
        for (int mi = 0; mi < 4; mi++)
#pragma unroll
            for (int nj = 0; nj < 4; nj++) {
                const int lc = lc0 + nj * 8;
#pragma unroll
                for (int half = 0; half < 2; half++) {
                    int rr = lr0 + mi * 16 + half * 8;
                    sV[lc * 136 + rr] = __float2half_rn(acc[mi][nj][half * 2 + 0]);
                    sV[(lc + 1) * 136 + rr] = __float2half_rn(acc[mi][nj][half * 2 + 1]);
                }
            }
        __syncthreads();
        for (int i = tid; i < 128 * 16; i += 256) {
            int row = i >> 4, seg = i & 15;
            int gn = bn + row;
            int hh = gn >> 6, dd = gn & 63;
            size_t dst = (size_t)(hh * DH + dd) * T_SEQ + bm + seg * 8;
            *(uint4*)(Vt + dst) = *(uint4*)(sV + row * 136 + seg * 8);
        }
    }
}

__global__ void __launch_bounds__(256, 2)
gemm_out(const __half* __restrict__ A, const __half* __restrict__ B,
         float* __restrict__ Cf) {
    extern __shared__ char smraw[];
    const uint32_t sb = smem_u32(smraw);

    const int tid = threadIdx.x;
    const int warp = tid >> 5;
    const int lane = tid & 31;
    const int bm = blockIdx.y * 128;
    const int bn = blockIdx.x * 128;
    const int wm = (warp >> 2) * 64;
    const int wn = (warp & 3) * 32;
    const int lrow = lane & 15;
    const int lseg = lane >> 4;

    float acc[4][4][4];
    gemm_main(sb, A, B, bm, bn, tid, wm, wn, lrow, lseg, acc);

    const int r0 = bm + wm + (lane >> 2);
    const int c0 = bn + wn + (lane & 3) * 2;
#pragma unroll
    for (int mi = 0; mi < 4; mi++)
#pragma unroll
        for (int nj = 0; nj < 4; nj++) {
            const int r = r0 + mi * 16;
            const int cc = c0 + nj * 8;
            float* d0 = Cf + (size_t)r * DMODEL + cc;
            float* d1 = Cf + (size_t)(r + 8) * DMODEL + cc;
            *(float2*)d0 = make_float2(acc[mi][nj][0], acc[mi][nj][1]);
            *(float2*)d1 = make_float2(acc[mi][nj][2], acc[mi][nj][3]);
        }
}

// ---------------------------------------------------------------------------
// fp16 HMMA sliding-window attention — R15 structure with a 3-stage K/V ring
// (56.3KB smem -> 4 CTAs/SM; grid 1024 -> 1.73 waves instead of 2.31).
// One sync per tile: prefetch ti+2 -> stage (ti+2)%3 == (ti-1)%3, which the
// iteration-ti barrier has drained. log2-domain softmax, boundary masks.
// ---------------------------------------------------------------------------
#define AT_ROWB 128
#define ATILE (64 * AT_ROWB)              // 8192
#define AOFF_K 0
#define AOFF_V ATILE
#define ASTAGE (2 * ATILE)                // 16384
#define ANSTAGE 3
#define AOFF_Q (ANSTAGE * ASTAGE)         // 49152
#define ATTN_SMEM (AOFF_Q + ATILE)        // 57344 (<= 58112 = 227KB/4)

__device__ __forceinline__ void attn_load_tile(
    uint32_t base, const __half* __restrict__ K16, const __half* __restrict__ Vt16,
    int h, int kt, int tid) {
#pragma unroll
    for (int i = 0; i < 4; i++) {
        int idx = tid + i * 128;
        int row = idx >> 3, seg = idx & 7;
        uint32_t off = SW128((uint32_t)(row * AT_ROWB + seg * 16));
        size_t ks = ((size_t)(h * T_SEQ + kt + row) << 6) + seg * 8;
        cp16(base + AOFF_K + off, K16 + ks);
        size_t vs = (size_t)(h * DH + row) * T_SEQ + kt + seg * 8;
        cp16(base + AOFF_V + off, Vt16 + vs);
    }
    CP_COMMIT();
}

__global__ void __launch_bounds__(128)
attn_mma(const __half* __restrict__ Q16, const __half* __restrict__ K16,
         const __half* __restrict__ Vt16, __half* __restrict__ AO) {
    extern __shared__ char smraw[];
    const uint32_t sb = smem_u32(smraw);
    const int tid = threadIdx.x;
    const int warp = tid >> 5;
    const int lane = tid & 31;
    const int h = blockIdx.y;
    const int q0 = blockIdx.x * 64;
    const int lrow = lane & 15;
    const int lseg = lane >> 4;

    const int kt_lo = (q0 >= WIN) ? (q0 - WIN) : 0;
    const int ntiles = (q0 - kt_lo) / 64 + 1;   // 1..5

    // prologue: Q, then up to 2 K/V tiles — all issued before any wait
#pragma unroll
    for (int i = 0; i < 4; i++) {
        int idx = tid + i * 128;
        int row = idx >> 3, seg = idx & 7;
        uint32_t dst = sb + AOFF_Q + SW128((uint32_t)(row * AT_ROWB + seg * 16));
        size_t qs = ((size_t)(h * T_SEQ + q0 + row) << 6) + seg * 8;
        cp16(dst, Q16 + qs);
    }
    CP_COMMIT();
    attn_load_tile(sb, K16, Vt16, h, kt_lo, tid);
    if (ntiles > 1) attn_load_tile(sb + ASTAGE, K16, Vt16, h, kt_lo + 64, tid);

    // wait for Q (K/V tile groups may stay in flight)
    if (ntiles > 1) { CP_WAIT(2); } else { CP_WAIT(1); }
    __syncthreads();

    uint32_t qf[4][4];
#pragma unroll
    for (int k = 0; k < 4; k++) {
        uint32_t ad = sb + AOFF_Q +
                      SW128((uint32_t)((warp * 16 + lrow) * AT_ROWB + k * 32 + lseg * 16));
        ldsm4(qf[k], ad);
    }

    float o[8][4];
#pragma unroll
    for (int j = 0; j < 8; j++)
#pragma unroll
        for (int e = 0; e < 4; e++) o[j][e] = 0.0f;
    float m0 = -1e30f, m1 = -1e30f, l0 = 0.0f, l1 = 0.0f;

    int stage = 0;                // ti % 3
    for (int ti = 0; ti < ntiles; ti++) {
        const int kt = kt_lo + ti * 64;
        if (ti + 1 < ntiles) { CP_WAIT(1); } else { CP_WAIT(0); }
        __syncthreads();

        // prefetch ti+2 into stage (ti+2)%3 == (ti-1)%3 (drained by barrier)
        if (ti + 2 < ntiles) {
            int ps = stage - 1;
            if (ps < 0) ps = 2;
            attn_load_tile(sb + (uint32_t)ps * ASTAGE, K16, Vt16, h, kt + 128, tid);
        }

        const uint32_t base = sb + (uint32_t)stage * ASTAGE;

        // ---- S = Q K^T (log2-domain scores) ----
        float sf[8][4];
#pragma unroll
        for (int j = 0; j < 8; j++)
#pragma unroll
            for (int e = 0; e < 4; e++) sf[j][e] = 0.0f;
#pragma unroll
        for (int kk = 0; kk < 4; kk++) {
            uint32_t bf[4][4];
#pragma unroll
            for (int n16 = 0; n16 < 4; n16++) {
                uint32_t ad = base + AOFF_K +
                    SW128((uint32_t)((n16 * 16 + lrow) * AT_ROWB + kk * 32 + lseg * 16));
                ldsm4(bf[n16], ad);
            }
#pragma unroll
            for (int j = 0; j < 8; j++) {
                const int nh = j >> 1, sub = j & 1;
                mmah(sf[j], qf[kk], bf[nh][sub], bf[nh][sub + 2]);
            }
        }

        // ---- mask ----
        const int r0 = q0 + warp * 16 + (lane >> 2);
        const int r1 = r0 + 8;
#pragma unroll
        for (int j = 0; j < 8; j++) {
            const int c0 = kt + 8 * j + (lane & 3) * 2;
            const int c1 = c0 + 1;
            if (c0 > r0 || c0 < r0 - WIN) sf[j][0] = -1e30f;
            if (c1 > r0 || c1 < r0 - WIN) sf[j][1] = -1e30f;
            if (c0 > r1 || c0 < r1 - WIN) sf[j][2] = -1e30f;
            if (c1 > r1 || c1 < r1 - WIN) sf[j][3] = -1e30f;
        }

        // ---- online softmax in log2 domain (raw ex2) ----
        float t0 = -1e30f, t1 = -1e30f;
#pragma unroll
        for (int j = 0; j < 8; j++) {
            t0 = fmaxf(t0, fmaxf(sf[j][0], sf[j][1]));
            t1 = fmaxf(t1, fmaxf(sf[j][2], sf[j][3]));
        }
        t0 = fmaxf(t0, __shfl_xor_sync(0xffffffffu, t0, 1));
        t0 = fmaxf(t0, __shfl_xor_sync(0xffffffffu, t0, 2));
        t1 = fmaxf(t1, __shfl_xor_sync(0xffffffffu, t1, 1));
        t1 = fmaxf(t1, __shfl_xor_sync(0xffffffffu, t1, 2));
        const float mn0 = fmaxf(m0, t0), mn1 = fmaxf(m1, t1);
        const float corr0 = ex2(m0 - mn0), corr1 = ex2(m1 - mn1);
        m0 = mn0;
        m1 = mn1;

        uint32_t ph[4][4];
        float s0 = 0.0f, s1 = 0.0f;
#pragma unroll
        for (int j = 0; j < 8; j++) {
            float p0 = ex2(sf[j][0] - m0);
            float p1 = ex2(sf[j][1] - m0);
            float p2 = ex2(sf[j][2] - m1);
            float p3 = ex2(sf[j][3] - m1);
            s0 += p0 + p1;
            s1 += p2 + p3;
            const int kk = j >> 1, pos = (j & 1) * 2;
            ph[kk][pos + 0] = packh(p0, p1);
            ph[kk][pos + 1] = packh(p2, p3);
        }
        s0 += __shfl_xor_sync(0xffffffffu, s0, 1);
        s0 += __shfl_xor_sync(0xffffffffu, s0, 2);
        s1 += __shfl_xor_sync(0xffffffffu, s1, 1);
        s1 += __shfl_xor_sync(0xffffffffu, s1, 2);
        l0 = l0 * corr0 + s0;
        l1 = l1 * corr1 + s1;
#pragma unroll
        for (int j = 0; j < 8; j++) {
            o[j][0] *= corr0;
            o[j][1] *= corr0;
            o[j][2] *= corr1;
            o[j][3] *= corr1;
        }

        // ---- O += P V ----
#pragma unroll
        for (int kk = 0; kk < 4; kk++) {
            uint32_t vf[4][4];
#pragma unroll
            for (int n16 = 0; n16 < 4; n16++) {
                uint32_t ad = base + AOFF_V +
                    SW128((uint32_t)((n16 * 16 + lrow) * AT_ROWB + kk * 32 + lseg * 16));
                ldsm4(vf[n16], ad);
            }
#pragma unroll
            for (int j = 0; j < 8; j++) {
                const int nh = j >> 1, sub = j & 1;
                mmah(o[j], ph[kk], vf[nh][sub], vf[nh][sub + 2]);
            }
        }
        stage = (stage == 2) ? 0 : stage + 1;
    }

    const float i0 = 1.0f / l0;
    const float i1 = 1.0f / l1;
    const int tr = q0 + warp * 16 + (lane >> 2);
#pragma unroll
    for (int j = 0; j < 8; j++) {
        const int d = 8 * j + (lane & 3) * 2;
        size_t a0 = (size_t)tr * DMODEL + h * DH + d;
        size_t a1 = (size_t)(tr + 8) * DMODEL + h * DH + d;
        *(uint32_t*)(AO + a0) = packh(o[j][0] * i0, o[j][1] * i0);
        *(uint32_t*)(AO + a1) = packh(o[j][2] * i1, o[j][3] * i1);
    }
}

// ---------------------------------------------------------------------------
extern "C" void kernel_launch(void* const* d_in, const int* in_sizes, int n_in,
                              void* d_out, int out_size) {
    const float* x  = (const float*)d_in[0];
    const float* Wq = (const float*)d_in[1];
    const float* Wk = (const float*)d_in[2];
    const float* Wv = (const float*)d_in[3];
    const float* Wo = (const float*)d_in[4];
    float* out = (float*)d_out;

    __half *px16, *pW16, *pao16, *pQ16, *pK16, *pVt16;
    cudaGetSymbolAddress((void**)&px16, g_x16);
    cudaGetSymbolAddress((void**)&pW16, g_W16);
    cudaGetSymbolAddress((void**)&pao16, g_ao16);
    cudaGetSymbolAddress((void**)&pQ16, g_Q16);
    cudaGetSymbolAddress((void**)&pK16, g_K16);
    cudaGetSymbolAddress((void**)&pVt16, g_Vt16);

    cudaFuncSetAttribute(gemm_qkv, cudaFuncAttributeMaxDynamicSharedMemorySize, GEMM_SMEM);
    cudaFuncSetAttribute(gemm_out, cudaFuncAttributeMaxDynamicSharedMemorySize, GEMM_SMEM);
    cudaFuncSetAttribute(attn_mma, cudaFuncAttributeMaxDynamicSharedMemorySize, ATTN_SMEM);

    const int WSZ = DMODEL * DMODEL;

    convAll<<<4096 + 4096, 256>>>(x, Wq, Wk, Wv, Wo, px16, pW16);

    dim3 qkvgrid(DMODEL / 128, T_SEQ / 128, 3);  // (8, 32, 3) = 768 CTAs
    gemm_qkv<<<qkvgrid, 256, GEMM_SMEM>>>(px16, pW16, pQ16, pK16, pVt16);

    dim3 agrid(T_SEQ / 64, NHEADS);  // (64, 16) = 1024 CTAs, 4/SM resident
    attn_mma<<<agrid, 128, ATTN_SMEM>>>(pQ16, pK16, pVt16, pao16);

    dim3 ogrid(DMODEL / 128, T_SEQ / 128);
    gemm_out<<<ogrid, 256, GEMM_SMEM>>>(pao16, pW16 + 3 * WSZ, out);
}